// round 2
// baseline (speedup 1.0000x reference)
#include <cuda_runtime.h>
#include <cuda_bf16.h>
#include <stdint.h>

#define D_DIM    64
#define K_CENT   512
#define BM       128
#define BN       128
#define KSTEPS   16          // K' = 256 bf16 (xh|xh|xl|xl), 16 k16 steps
#define NCHUNK   32          // 256 halves/row = 32 chunks of 16B
#define NTHREADS 256

// SMEM byte offsets
#define SM_A     0           // 128 x 256 bf16 = 65536
#define SM_B     65536       // 128 x 256 bf16 = 65536
#define SM_X2    131072      // 128 f32
#define SM_C2    131584      // 128 f32 (this CTA's N-slice)
#define SM_BETA  132096      // 128 f32
#define SM_TOTAL 132608

// Center image: row n = [ch(0:64) | cl | ch | cl], 256 bf16 per row
__device__ __align__(16) __nv_bfloat16 g_cbf[K_CENT * 256];
__device__ float g_c2[K_CENT];

// ---------------- helpers ----------------
static __device__ __forceinline__ uint32_t smem_u32(const void* p) {
    uint32_t a;
    asm("{ .reg .u64 t; cvta.to.shared.u64 t, %1; cvt.u32.u64 %0, t; }" : "=r"(a) : "l"(p));
    return a;
}

// XOR swizzle on 16B chunks within groups of 8 (conflict-free ldmatrix & STS)
static __device__ __forceinline__ uint32_t sw_off(uint32_t row, uint32_t ch) {
    return ((row << 5) + (ch & 0xFFFFFFF8u) + ((ch & 7u) ^ (row & 7u))) << 4;
}

static __device__ __forceinline__ uint32_t pack_bf2(__nv_bfloat16 a, __nv_bfloat16 b) {
    __nv_bfloat162 t; t.x = a; t.y = b;
    return *reinterpret_cast<uint32_t*>(&t);
}

static __device__ __forceinline__ void ldsm4(uint32_t* r, uint32_t addr) {
    asm volatile("ldmatrix.sync.aligned.m8n8.x4.shared.b16 {%0,%1,%2,%3}, [%4];"
                 : "=r"(r[0]), "=r"(r[1]), "=r"(r[2]), "=r"(r[3]) : "r"(addr));
}

static __device__ __forceinline__ void mma16816(float* c, const uint32_t* a,
                                                uint32_t b0, uint32_t b1) {
    asm volatile(
        "mma.sync.aligned.m16n8k16.row.col.f32.bf16.bf16.f32 "
        "{%0,%1,%2,%3}, {%4,%5,%6,%7}, {%8,%9}, {%0,%1,%2,%3};"
        : "+f"(c[0]), "+f"(c[1]), "+f"(c[2]), "+f"(c[3])
        : "r"(a[0]), "r"(a[1]), "r"(a[2]), "r"(a[3]), "r"(b0), "r"(b1));
}

// exp(-t), t >= 0, denormal-correct even under fast-math (exp2f range-safe + ldexpf)
static __device__ __forceinline__ float exp_neg(float t) {
    float a = -t * 1.4426950408889634f;   // log2(e)
    float n = rintf(a);
    float f = a - n;                      // |f| <= 0.5, exact
    float p = exp2f(f);                   // result in [0.707, 1.414]
    return ldexpf(p, (int)n);             // correct gradual underflow
}

// ---------------- prep: bf16 hi/lo center image + c2 ----------------
__global__ void rbf_prep(const float* __restrict__ centers) {
    int n = blockIdx.x * blockDim.x + threadIdx.x;
    if (n >= K_CENT) return;
    const float* c = centers + (size_t)n * D_DIM;
    __nv_bfloat16* row = g_cbf + (size_t)n * 256;
    float a0 = 0.f, a1 = 0.f;
    for (int k = 0; k < D_DIM; k += 2) {
        float v0 = c[k], v1 = c[k + 1];
        a0 += v0 * v0; a1 += v1 * v1;
        __nv_bfloat16 h0 = __float2bfloat16(v0);
        __nv_bfloat16 h1 = __float2bfloat16(v1);
        __nv_bfloat16 l0 = __float2bfloat16(v0 - __bfloat162float(h0));
        __nv_bfloat16 l1 = __float2bfloat16(v1 - __bfloat162float(h1));
        row[k] = h0;       row[k + 1] = h1;        // block 0: ch
        row[64 + k] = l0;  row[64 + k + 1] = l1;   // block 1: cl
        row[128 + k] = h0; row[128 + k + 1] = h1;  // block 2: ch
        row[192 + k] = l0; row[192 + k + 1] = l1;  // block 3: cl
    }
    g_c2[n] = a0 + a1;
}

// ---------------- main ----------------
__global__ void __launch_bounds__(NTHREADS, 1)
rbf_main(const float* __restrict__ x, const float* __restrict__ betas,
         float* __restrict__ out) {
    extern __shared__ char smem[];
    uint32_t sb = smem_u32(smem);
    int tid = threadIdx.x;
    int lane = tid & 31;
    int wid = tid >> 5;
    int warp_m = wid & 3;        // 4 warps along M (32 rows each)
    int warp_n = wid >> 2;       // 2 warps along N (64 cols each)
    int m0 = blockIdx.y * BM;
    int n0 = blockIdx.x * BN;

    const float* xt = x + (size_t)m0 * D_DIM;

    // A tile: fp32 -> bf16 hi/lo, k-blocks [xh|xh|xl|xl], swizzled STS
    for (int i = tid; i < BM * 8; i += NTHREADS) {
        int r = i >> 3, c = i & 7;                 // c indexes 8-float chunk of the 64 dims
        const float4* p = reinterpret_cast<const float4*>(xt + (size_t)r * D_DIM + c * 8);
        float4 v0 = p[0], v1 = p[1];
        float f[8] = {v0.x, v0.y, v0.z, v0.w, v1.x, v1.y, v1.z, v1.w};
        uint32_t hv[4], lv[4];
        #pragma unroll
        for (int j = 0; j < 4; j++) {
            __nv_bfloat16 h0 = __float2bfloat16(f[2 * j]);
            __nv_bfloat16 h1 = __float2bfloat16(f[2 * j + 1]);
            __nv_bfloat16 l0 = __float2bfloat16(f[2 * j] - __bfloat162float(h0));
            __nv_bfloat16 l1 = __float2bfloat16(f[2 * j + 1] - __bfloat162float(h1));
            hv[j] = pack_bf2(h0, h1);
            lv[j] = pack_bf2(l0, l1);
        }
        uint4 H = make_uint4(hv[0], hv[1], hv[2], hv[3]);
        uint4 L = make_uint4(lv[0], lv[1], lv[2], lv[3]);
        *reinterpret_cast<uint4*>(smem + SM_A + sw_off(r, c))      = H;
        *reinterpret_cast<uint4*>(smem + SM_A + sw_off(r, c + 8))  = H;
        *reinterpret_cast<uint4*>(smem + SM_A + sw_off(r, c + 16)) = L;
        *reinterpret_cast<uint4*>(smem + SM_A + sw_off(r, c + 24)) = L;
    }

    // B tile: copy pre-built rows n0..n0+127 (L2-resident), swizzled STS
    {
        const uint4* bsrc = reinterpret_cast<const uint4*>(g_cbf + (size_t)n0 * 256);
        for (int i = tid; i < BN * NCHUNK; i += NTHREADS) {
            int r = i >> 5, c = i & 31;
            *reinterpret_cast<uint4*>(smem + SM_B + sw_off(r, c)) = bsrc[r * 32 + c];
        }
    }

    // c2 / beta slices
    {
        float* sc2 = reinterpret_cast<float*>(smem + SM_C2);
        float* sbt = reinterpret_cast<float*>(smem + SM_BETA);
        for (int i = tid; i < BN; i += NTHREADS) {
            sc2[i] = g_c2[n0 + i];
            sbt[i] = betas[n0 + i];
        }
    }

    // x2 per row (fixed-order, deterministic)
    if (tid < BM) {
        const float4* xr = reinterpret_cast<const float4*>(xt + (size_t)tid * D_DIM);
        float4 a = make_float4(0.f, 0.f, 0.f, 0.f);
        #pragma unroll
        for (int q = 0; q < 16; q++) {
            float4 v = xr[q];
            a.x += v.x * v.x; a.y += v.y * v.y; a.z += v.z * v.z; a.w += v.w * v.w;
        }
        reinterpret_cast<float*>(smem + SM_X2)[tid] = (a.x + a.y) + (a.z + a.w);
    }

    __syncthreads();

    // ---- mainloop: 16 k16 steps, fully unrolled ----
    uint32_t rowA = warp_m * 32 + (lane & 15);
    uint32_t chA  = (uint32_t)(lane >> 4);
    uint32_t rowB = warp_n * 64 + (lane & 7) + ((lane >> 4) << 3);
    uint32_t chB  = (uint32_t)((lane >> 3) & 1);

    float acc[2][8][4];
    #pragma unroll
    for (int mi = 0; mi < 2; mi++)
        #pragma unroll
        for (int ni = 0; ni < 8; ni++)
            #pragma unroll
            for (int q = 0; q < 4; q++) acc[mi][ni][q] = 0.f;

    #pragma unroll
    for (int ks = 0; ks < KSTEPS; ks++) {
        uint32_t a[2][4], b[4][4];
        #pragma unroll
        for (int mi = 0; mi < 2; mi++)
            ldsm4(a[mi], sb + SM_A + sw_off(rowA + mi * 16, 2 * ks + chA));
        #pragma unroll
        for (int nq = 0; nq < 4; nq++)
            ldsm4(b[nq], sb + SM_B + sw_off(rowB + nq * 16, 2 * ks + chB));
        #pragma unroll
        for (int mi = 0; mi < 2; mi++)
            #pragma unroll
            for (int ni = 0; ni < 8; ni++)
                mma16816(acc[mi][ni], a[mi], b[ni >> 1][(ni & 1) * 2],
                         b[ni >> 1][(ni & 1) * 2 + 1]);
    }

    // ---- epilogue: d2 -> guarded exp -> direct global store ----
    const float* sx2 = reinterpret_cast<const float*>(smem + SM_X2);
    const float* sc2 = reinterpret_cast<const float*>(smem + SM_C2);
    const float* sbt = reinterpret_cast<const float*>(smem + SM_BETA);
    int rbase = warp_m * 32 + (lane >> 2);
    int cbase = warp_n * 64 + (lane & 3) * 2;
    float* outp = out + (size_t)m0 * K_CENT + n0;

    #pragma unroll
    for (int mi = 0; mi < 2; mi++) {
        #pragma unroll
        for (int h = 0; h < 2; h++) {
            int row = rbase + mi * 16 + h * 8;
            float x2r = sx2[row];
            float* orow = outp + (size_t)row * K_CENT;
            #pragma unroll
            for (int ni = 0; ni < 8; ni++) {
                int col = cbase + ni * 8;
                float dot0 = acc[mi][ni][h * 2 + 0];
                float dot1 = acc[mi][ni][h * 2 + 1];
                float d0 = fmaxf(fmaf(-2.f, dot0, x2r + sc2[col]), 0.f);
                float d1 = fmaxf(fmaf(-2.f, dot1, x2r + sc2[col + 1]), 0.f);
                float t0 = sbt[col] * d0;
                float t1 = sbt[col + 1] * d1;
                float e0 = 0.f, e1 = 0.f;
                if (t0 < 104.5f) e0 = exp_neg(t0);   // below denormal floor -> 0, skip MUFU
                if (t1 < 104.5f) e1 = exp_neg(t1);
                *reinterpret_cast<float2*>(orow + col) = make_float2(e0, e1);
            }
        }
    }
}

extern "C" void kernel_launch(void* const* d_in, const int* in_sizes, int n_in,
                              void* d_out, int out_size) {
    const float* x       = (const float*)d_in[0];
    const float* centers = (const float*)d_in[1];
    const float* betas   = (const float*)d_in[2];
    float* out = (float*)d_out;

    int B = in_sizes[0] / D_DIM;   // 65536
    cudaFuncSetAttribute(rbf_main, cudaFuncAttributeMaxDynamicSharedMemorySize, SM_TOTAL);

    rbf_prep<<<(K_CENT + 255) / 256, 256>>>(centers);
    dim3 grid(K_CENT / BN, B / BM);   // N fastest: CTAs sharing an A tile are adjacent
    rbf_main<<<grid, NTHREADS, SM_TOTAL>>>(x, betas, out);
}

// round 3
// speedup vs baseline: 1.8373x; 1.8373x over previous
#include <cuda_runtime.h>
#include <cuda_bf16.h>
#include <stdint.h>

#define D_DIM    64
#define K_CENT   512
#define BM       64
#define BN       128
#define KSTEPS   16          // K' = 256 bf16 (xh|xh|xl|xl), 16 k16 steps
#define NCHUNK   32          // 256 halves/row = 32 chunks of 16B
#define NTHREADS 256

// SMEM byte offsets
#define SM_A     0           // 64 x 256 bf16  = 32768
#define SM_B     32768       // 128 x 256 bf16 = 65536
#define SM_X2    98304       // 64 f32
#define SM_C2    98560       // 128 f32
#define SM_BETA  99072       // 128 f32
#define SM_TOTAL 99584

// Center image: row n = [ch(0:64) | cl | ch | cl], 256 bf16 per row
__device__ __align__(16) __nv_bfloat16 g_cbf[K_CENT * 256];
__device__ float g_c2[K_CENT];

// ---------------- helpers ----------------
static __device__ __forceinline__ uint32_t smem_u32(const void* p) {
    uint32_t a;
    asm("{ .reg .u64 t; cvta.to.shared.u64 t, %1; cvt.u32.u64 %0, t; }" : "=r"(a) : "l"(p));
    return a;
}

// XOR swizzle on 16B chunks within groups of 8 (conflict-free ldmatrix & STS)
static __device__ __forceinline__ uint32_t sw_off(uint32_t row, uint32_t ch) {
    return ((row << 5) + (ch & 0xFFFFFFF8u) + ((ch & 7u) ^ (row & 7u))) << 4;
}

static __device__ __forceinline__ uint32_t pack_bf2(__nv_bfloat16 a, __nv_bfloat16 b) {
    __nv_bfloat162 t; t.x = a; t.y = b;
    return *reinterpret_cast<uint32_t*>(&t);
}

static __device__ __forceinline__ void ldsm4(uint32_t* r, uint32_t addr) {
    asm volatile("ldmatrix.sync.aligned.m8n8.x4.shared.b16 {%0,%1,%2,%3}, [%4];"
                 : "=r"(r[0]), "=r"(r[1]), "=r"(r[2]), "=r"(r[3]) : "r"(addr));
}

static __device__ __forceinline__ void mma16816(float* c, const uint32_t* a,
                                                uint32_t b0, uint32_t b1) {
    asm volatile(
        "mma.sync.aligned.m16n8k16.row.col.f32.bf16.bf16.f32 "
        "{%0,%1,%2,%3}, {%4,%5,%6,%7}, {%8,%9}, {%0,%1,%2,%3};"
        : "+f"(c[0]), "+f"(c[1]), "+f"(c[2]), "+f"(c[3])
        : "r"(a[0]), "r"(a[1]), "r"(a[2]), "r"(a[3]), "r"(b0), "r"(b1));
}

static __device__ __forceinline__ void cp16(uint32_t dst, const void* src) {
    asm volatile("cp.async.cg.shared.global [%0], [%1], 16;"
                 :: "r"(dst), "l"(src) : "memory");
}

// exp(-t), t >= 0, denormal-correct even under fast-math (exp2f range-safe + ldexpf)
static __device__ __forceinline__ float exp_neg(float t) {
    float a = -t * 1.4426950408889634f;   // log2(e)
    float n = rintf(a);
    float f = a - n;                      // |f| <= 0.5, exact
    float p = exp2f(f);                   // result in [0.707, 1.414]
    return ldexpf(p, (int)n);             // correct gradual underflow
}

// ---------------- prep: bf16 hi/lo center image + c2 ----------------
__global__ void rbf_prep(const float* __restrict__ centers) {
    int n = blockIdx.x * blockDim.x + threadIdx.x;
    if (n >= K_CENT) return;
    const float* c = centers + (size_t)n * D_DIM;
    __nv_bfloat16* row = g_cbf + (size_t)n * 256;
    float a0 = 0.f, a1 = 0.f;
    for (int k = 0; k < D_DIM; k += 2) {
        float v0 = c[k], v1 = c[k + 1];
        a0 += v0 * v0; a1 += v1 * v1;
        __nv_bfloat16 h0 = __float2bfloat16(v0);
        __nv_bfloat16 h1 = __float2bfloat16(v1);
        __nv_bfloat16 l0 = __float2bfloat16(v0 - __bfloat162float(h0));
        __nv_bfloat16 l1 = __float2bfloat16(v1 - __bfloat162float(h1));
        row[k] = h0;       row[k + 1] = h1;        // block 0: ch
        row[64 + k] = l0;  row[64 + k + 1] = l1;   // block 1: cl
        row[128 + k] = h0; row[128 + k + 1] = h1;  // block 2: ch
        row[192 + k] = l0; row[192 + k + 1] = l1;  // block 3: cl
    }
    g_c2[n] = a0 + a1;
}

// ---------------- main ----------------
__global__ void __launch_bounds__(NTHREADS, 2)
rbf_main(const float* __restrict__ x, const float* __restrict__ betas,
         float* __restrict__ out) {
    extern __shared__ char smem[];
    uint32_t sb = smem_u32(smem);
    int tid = threadIdx.x;
    int lane = tid & 31;
    int wid = tid >> 5;
    int warp_m = wid & 1;        // 2 warps along M (32 rows each)
    int warp_n = wid >> 1;       // 4 warps along N (32 cols each)
    int m0 = blockIdx.y * BM;
    int n0 = blockIdx.x * BN;

    const float* xt = x + (size_t)m0 * D_DIM;

    // B tile via cp.async (L2-resident pre-built image), swizzled dst — issued first
    {
        const char* bsrc = reinterpret_cast<const char*>(g_cbf + (size_t)n0 * 256);
        #pragma unroll
        for (int j = 0; j < (BN * NCHUNK) / NTHREADS; j++) {
            int i = j * NTHREADS + tid;
            int r = i >> 5, c = i & 31;
            cp16(sb + SM_B + sw_off(r, c), bsrc + (size_t)r * 512 + c * 16);
        }
        asm volatile("cp.async.commit_group;" ::: "memory");
    }

    // A tile: fp32 -> bf16 hi/lo, k-blocks [xh|xh|xl|xl], swizzled STS
    #pragma unroll
    for (int j = 0; j < (BM * 8) / NTHREADS; j++) {
        int i = j * NTHREADS + tid;
        int r = i >> 3, c = i & 7;                 // c: 8-float chunk of the 64 dims
        const float4* p = reinterpret_cast<const float4*>(xt + (size_t)r * D_DIM + c * 8);
        float4 v0 = p[0], v1 = p[1];
        float f[8] = {v0.x, v0.y, v0.z, v0.w, v1.x, v1.y, v1.z, v1.w};
        uint32_t hv[4], lv[4];
        #pragma unroll
        for (int j2 = 0; j2 < 4; j2++) {
            __nv_bfloat16 h0 = __float2bfloat16(f[2 * j2]);
            __nv_bfloat16 h1 = __float2bfloat16(f[2 * j2 + 1]);
            __nv_bfloat16 l0 = __float2bfloat16(f[2 * j2] - __bfloat162float(h0));
            __nv_bfloat16 l1 = __float2bfloat16(f[2 * j2 + 1] - __bfloat162float(h1));
            hv[j2] = pack_bf2(h0, h1);
            lv[j2] = pack_bf2(l0, l1);
        }
        uint4 H = make_uint4(hv[0], hv[1], hv[2], hv[3]);
        uint4 L = make_uint4(lv[0], lv[1], lv[2], lv[3]);
        *reinterpret_cast<uint4*>(smem + SM_A + sw_off(r, c))      = H;
        *reinterpret_cast<uint4*>(smem + SM_A + sw_off(r, c + 8))  = H;
        *reinterpret_cast<uint4*>(smem + SM_A + sw_off(r, c + 16)) = L;
        *reinterpret_cast<uint4*>(smem + SM_A + sw_off(r, c + 24)) = L;
    }

    // c2 / beta slices
    {
        float* sc2 = reinterpret_cast<float*>(smem + SM_C2);
        float* sbt = reinterpret_cast<float*>(smem + SM_BETA);
        if (tid < BN) {
            sc2[tid] = g_c2[n0 + tid];
            sbt[tid] = betas[n0 + tid];
        }
    }

    // x2 per row (fixed-order, deterministic)
    if (tid < BM) {
        const float4* xr = reinterpret_cast<const float4*>(xt + (size_t)tid * D_DIM);
        float4 a = make_float4(0.f, 0.f, 0.f, 0.f);
        #pragma unroll
        for (int q = 0; q < 16; q++) {
            float4 v = xr[q];
            a.x += v.x * v.x; a.y += v.y * v.y; a.z += v.z * v.z; a.w += v.w * v.w;
        }
        reinterpret_cast<float*>(smem + SM_X2)[tid] = (a.x + a.y) + (a.z + a.w);
    }

    asm volatile("cp.async.wait_group 0;" ::: "memory");
    __syncthreads();

    // ---- mainloop: 16 k16 steps, fully unrolled ----
    uint32_t rowA = warp_m * 32 + (lane & 15);
    uint32_t chA  = (uint32_t)(lane >> 4);
    uint32_t rowB = warp_n * 32 + (lane & 7) + ((lane >> 4) << 3);
    uint32_t chB  = (uint32_t)((lane >> 3) & 1);

    float acc[2][4][4];
    #pragma unroll
    for (int mi = 0; mi < 2; mi++)
        #pragma unroll
        for (int ni = 0; ni < 4; ni++)
            #pragma unroll
            for (int q = 0; q < 4; q++) acc[mi][ni][q] = 0.f;

    #pragma unroll
    for (int ks = 0; ks < KSTEPS; ks++) {
        uint32_t a[2][4], b[2][4];
        #pragma unroll
        for (int mi = 0; mi < 2; mi++)
            ldsm4(a[mi], sb + SM_A + sw_off(rowA + mi * 16, 2 * ks + chA));
        #pragma unroll
        for (int nq = 0; nq < 2; nq++)
            ldsm4(b[nq], sb + SM_B + sw_off(rowB + nq * 16, 2 * ks + chB));
        #pragma unroll
        for (int mi = 0; mi < 2; mi++)
            #pragma unroll
            for (int ni = 0; ni < 4; ni++)
                mma16816(acc[mi][ni], a[mi], b[ni >> 1][(ni & 1) * 2],
                         b[ni >> 1][(ni & 1) * 2 + 1]);
    }

    // ---- epilogue: d2 -> guarded exp -> streaming global store ----
    const float* sx2 = reinterpret_cast<const float*>(smem + SM_X2);
    const float* sc2 = reinterpret_cast<const float*>(smem + SM_C2);
    const float* sbt = reinterpret_cast<const float*>(smem + SM_BETA);
    int rbase = warp_m * 32 + (lane >> 2);
    int cbase = warp_n * 32 + (lane & 3) * 2;
    float* outp = out + (size_t)m0 * K_CENT + n0;

    #pragma unroll
    for (int mi = 0; mi < 2; mi++) {
        #pragma unroll
        for (int h = 0; h < 2; h++) {
            int row = rbase + mi * 16 + h * 8;
            float x2r = sx2[row];
            float* orow = outp + (size_t)row * K_CENT;
            #pragma unroll
            for (int ni = 0; ni < 4; ni++) {
                int col = cbase + ni * 8;
                float dot0 = acc[mi][ni][h * 2 + 0];
                float dot1 = acc[mi][ni][h * 2 + 1];
                float d0 = fmaxf(fmaf(-2.f, dot0, x2r + sc2[col]), 0.f);
                float d1 = fmaxf(fmaf(-2.f, dot1, x2r + sc2[col + 1]), 0.f);
                float t0 = sbt[col] * d0;
                float t1 = sbt[col + 1] * d1;
                float e0 = 0.f, e1 = 0.f;
                if (t0 < 104.5f) e0 = exp_neg(t0);   // below denormal floor -> 0
                if (t1 < 104.5f) e1 = exp_neg(t1);
                __stcs(reinterpret_cast<float2*>(orow + col), make_float2(e0, e1));
            }
        }
    }
}

extern "C" void kernel_launch(void* const* d_in, const int* in_sizes, int n_in,
                              void* d_out, int out_size) {
    const float* x       = (const float*)d_in[0];
    const float* centers = (const float*)d_in[1];
    const float* betas   = (const float*)d_in[2];
    float* out = (float*)d_out;

    int B = in_sizes[0] / D_DIM;   // 65536
    cudaFuncSetAttribute(rbf_main, cudaFuncAttributeMaxDynamicSharedMemorySize, SM_TOTAL);

    rbf_prep<<<(K_CENT + 255) / 256, 256>>>(centers);
    dim3 grid(K_CENT / BN, B / BM);   // N fastest: CTAs sharing an A tile are adjacent
    rbf_main<<<grid, NTHREADS, SM_TOTAL>>>(x, betas, out);
}

// round 4
// speedup vs baseline: 2.1800x; 1.1865x over previous
#include <cuda_runtime.h>
#include <cuda_bf16.h>
#include <stdint.h>

#define D_DIM    64
#define K_CENT   512
#define BM       128
#define BN       128
#define NTHREADS 256

// SMEM byte offsets (K'=128 bf16 per row = 256 B = 16 chunks of 16B)
#define SM_A     0           // 128 x 128 bf16 = 32768
#define SM_B     32768       // 128 x 128 bf16 = 32768
#define SM_C2    65536       // 128 f32
#define SM_BETA  66048       // 128 f32
#define SM_X2    66560       // 128 f32
#define SM_TOTAL 67072

// Global images: rows are [hi(64) | lo(64)] bf16
__device__ __align__(16) __nv_bfloat16 g_cbf[K_CENT * 128];      // 128 KB
__device__ __align__(16) __nv_bfloat16 g_ximg[65536 * 128];      // 16 MB
__device__ float g_c2[K_CENT];
__device__ float g_x2[65536];

// ---------------- helpers ----------------
static __device__ __forceinline__ uint32_t smem_u32(const void* p) {
    uint32_t a;
    asm("{ .reg .u64 t; cvta.to.shared.u64 t, %1; cvt.u32.u64 %0, t; }" : "=r"(a) : "l"(p));
    return a;
}

// XOR swizzle on 16B chunks (16 chunks/row), conflict-free ldmatrix/cp.async
static __device__ __forceinline__ uint32_t sw_off(uint32_t row, uint32_t ch) {
    return ((row << 4) + (ch & 0xFFFFFFF8u) + ((ch & 7u) ^ (row & 7u))) << 4;
}

static __device__ __forceinline__ uint32_t pack_bf2(__nv_bfloat16 a, __nv_bfloat16 b) {
    __nv_bfloat162 t; t.x = a; t.y = b;
    return *reinterpret_cast<uint32_t*>(&t);
}

static __device__ __forceinline__ void ldsm4(uint32_t* r, uint32_t addr) {
    asm volatile("ldmatrix.sync.aligned.m8n8.x4.shared.b16 {%0,%1,%2,%3}, [%4];"
                 : "=r"(r[0]), "=r"(r[1]), "=r"(r[2]), "=r"(r[3]) : "r"(addr));
}

static __device__ __forceinline__ void mma16816(float* c, const uint32_t* a,
                                                uint32_t b0, uint32_t b1) {
    asm volatile(
        "mma.sync.aligned.m16n8k16.row.col.f32.bf16.bf16.f32 "
        "{%0,%1,%2,%3}, {%4,%5,%6,%7}, {%8,%9}, {%0,%1,%2,%3};"
        : "+f"(c[0]), "+f"(c[1]), "+f"(c[2]), "+f"(c[3])
        : "r"(a[0]), "r"(a[1]), "r"(a[2]), "r"(a[3]), "r"(b0), "r"(b1));
}

static __device__ __forceinline__ void cp16(uint32_t dst, const void* src) {
    asm volatile("cp.async.cg.shared.global [%0], [%1], 16;"
                 :: "r"(dst), "l"(src) : "memory");
}

// exp(-t), t >= 0, denormal-correct even under fast-math
static __device__ __forceinline__ float exp_neg(float t) {
    float a = -t * 1.4426950408889634f;
    float n = rintf(a);
    float f = a - n;
    float p = exp2f(f);
    return ldexpf(p, (int)n);
}

// ---------------- prep 1: centers -> [ch|cl] image + c2 ----------------
__global__ void rbf_prep_c(const float* __restrict__ centers) {
    int n = blockIdx.x * blockDim.x + threadIdx.x;
    if (n >= K_CENT) return;
    const float* c = centers + (size_t)n * D_DIM;
    __nv_bfloat16* row = g_cbf + (size_t)n * 128;
    float a0 = 0.f, a1 = 0.f;
    for (int k = 0; k < D_DIM; k += 2) {
        float v0 = c[k], v1 = c[k + 1];
        a0 += v0 * v0; a1 += v1 * v1;
        __nv_bfloat16 h0 = __float2bfloat16(v0);
        __nv_bfloat16 h1 = __float2bfloat16(v1);
        row[k] = h0; row[k + 1] = h1;
        row[64 + k]     = __float2bfloat16(v0 - __bfloat162float(h0));
        row[64 + k + 1] = __float2bfloat16(v1 - __bfloat162float(h1));
    }
    g_c2[n] = a0 + a1;
}

// ---------------- prep 2: x -> [xh|xl] image + x2 ----------------
// thread t: row = t/8, handles 8 consecutive floats (seg = t%8)
__global__ void rbf_prep_x(const float* __restrict__ x) {
    int t = blockIdx.x * blockDim.x + threadIdx.x;
    int row = t >> 3, seg = t & 7;
    const float4* p = reinterpret_cast<const float4*>(x + (size_t)row * D_DIM + seg * 8);
    float4 v0 = p[0], v1 = p[1];
    float f[8] = {v0.x, v0.y, v0.z, v0.w, v1.x, v1.y, v1.z, v1.w};
    uint32_t hv[4], lv[4];
    float s = 0.f;
    #pragma unroll
    for (int j = 0; j < 4; j++) {
        float a = f[2 * j], b = f[2 * j + 1];
        s += a * a + b * b;
        __nv_bfloat16 h0 = __float2bfloat16(a);
        __nv_bfloat16 h1 = __float2bfloat16(b);
        __nv_bfloat16 l0 = __float2bfloat16(a - __bfloat162float(h0));
        __nv_bfloat16 l1 = __float2bfloat16(b - __bfloat162float(h1));
        hv[j] = pack_bf2(h0, h1);
        lv[j] = pack_bf2(l0, l1);
    }
    uint4* rowp = reinterpret_cast<uint4*>(g_ximg + (size_t)row * 128);
    rowp[seg]     = make_uint4(hv[0], hv[1], hv[2], hv[3]);
    rowp[8 + seg] = make_uint4(lv[0], lv[1], lv[2], lv[3]);
    s += __shfl_down_sync(0xFFFFFFFFu, s, 4, 8);
    s += __shfl_down_sync(0xFFFFFFFFu, s, 2, 8);
    s += __shfl_down_sync(0xFFFFFFFFu, s, 1, 8);
    if (seg == 0) g_x2[row] = s;
}

// ---------------- main ----------------
__global__ void __launch_bounds__(NTHREADS, 2)
rbf_main(const float* __restrict__ betas, float* __restrict__ out) {
    extern __shared__ char smem[];
    uint32_t sb = smem_u32(smem);
    int tid = threadIdx.x;
    int lane = tid & 31;
    int wid = tid >> 5;
    int warp_m = wid & 1;        // 2 warps along M (64 rows each)
    int warp_n = wid >> 1;       // 4 warps along N (32 cols each)
    int m0 = blockIdx.y * BM;
    int n0 = blockIdx.x * BN;

    // A + B tiles via cp.async into swizzled smem (both images prebuilt)
    {
        const char* asrc = reinterpret_cast<const char*>(g_ximg + (size_t)m0 * 128);
        const char* bsrc = reinterpret_cast<const char*>(g_cbf + (size_t)n0 * 128);
        #pragma unroll
        for (int j = 0; j < 8; j++) {
            int i = j * NTHREADS + tid;
            int r = i >> 4, c = i & 15;
            cp16(sb + SM_A + sw_off(r, c), asrc + (size_t)r * 256 + c * 16);
        }
        #pragma unroll
        for (int j = 0; j < 8; j++) {
            int i = j * NTHREADS + tid;
            int r = i >> 4, c = i & 15;
            cp16(sb + SM_B + sw_off(r, c), bsrc + (size_t)r * 256 + c * 16);
        }
        asm volatile("cp.async.commit_group;" ::: "memory");
    }

    // scalar tables
    if (tid < BN) {
        reinterpret_cast<float*>(smem + SM_C2)[tid]   = g_c2[n0 + tid];
        reinterpret_cast<float*>(smem + SM_BETA)[tid] = betas[n0 + tid];
    }
    if (tid < BM) {
        reinterpret_cast<float*>(smem + SM_X2)[tid] = g_x2[m0 + tid];
    }

    asm volatile("cp.async.wait_group 0;" ::: "memory");
    __syncthreads();

    // ---- mainloop: 8 physical ksteps; each A frag used against B(s) and B((s+4)&7) ----
    uint32_t rowA = warp_m * 64 + (lane & 15);
    uint32_t chA  = (uint32_t)(lane >> 4);
    uint32_t rowB = warp_n * 32 + (lane & 7) + ((lane >> 4) << 3);
    uint32_t chB  = (uint32_t)((lane >> 3) & 1);

    float acc[4][4][4];
    #pragma unroll
    for (int mi = 0; mi < 4; mi++)
        #pragma unroll
        for (int ni = 0; ni < 4; ni++)
            #pragma unroll
            for (int q = 0; q < 4; q++) acc[mi][ni][q] = 0.f;

    #pragma unroll
    for (int s = 0; s < 8; s++) {
        int s2 = (s + 4) & 7;                      // half-swapped pairing
        uint32_t a[4][4], b1[2][4], b2[2][4];
        #pragma unroll
        for (int mi = 0; mi < 4; mi++)
            ldsm4(a[mi], sb + SM_A + sw_off(rowA + mi * 16, 2 * s + chA));
        #pragma unroll
        for (int nq = 0; nq < 2; nq++)
            ldsm4(b1[nq], sb + SM_B + sw_off(rowB + nq * 16, 2 * s + chB));
        #pragma unroll
        for (int nq = 0; nq < 2; nq++)
            ldsm4(b2[nq], sb + SM_B + sw_off(rowB + nq * 16, 2 * s2 + chB));
        #pragma unroll
        for (int mi = 0; mi < 4; mi++)
            #pragma unroll
            for (int ni = 0; ni < 4; ni++)
                mma16816(acc[mi][ni], a[mi], b1[ni >> 1][(ni & 1) * 2],
                         b1[ni >> 1][(ni & 1) * 2 + 1]);
        #pragma unroll
        for (int mi = 0; mi < 4; mi++)
            #pragma unroll
            for (int ni = 0; ni < 4; ni++)
                mma16816(acc[mi][ni], a[mi], b2[ni >> 1][(ni & 1) * 2],
                         b2[ni >> 1][(ni & 1) * 2 + 1]);
    }

    // ---- epilogue: d2 -> guarded exp -> streaming stores ----
    const float* sx2 = reinterpret_cast<const float*>(smem + SM_X2);
    const float* sc2 = reinterpret_cast<const float*>(smem + SM_C2);
    const float* sbt = reinterpret_cast<const float*>(smem + SM_BETA);
    int rbase = warp_m * 64 + (lane >> 2);
    int cbase = warp_n * 32 + (lane & 3) * 2;
    float* outp = out + (size_t)m0 * K_CENT + n0;

    #pragma unroll
    for (int mi = 0; mi < 4; mi++) {
        #pragma unroll
        for (int h = 0; h < 2; h++) {
            int row = rbase + mi * 16 + h * 8;
            float x2r = sx2[row];
            float* orow = outp + (size_t)row * K_CENT;
            #pragma unroll
            for (int ni = 0; ni < 4; ni++) {
                int col = cbase + ni * 8;
                float dot0 = acc[mi][ni][h * 2 + 0];
                float dot1 = acc[mi][ni][h * 2 + 1];
                float d0 = fmaxf(fmaf(-2.f, dot0, x2r + sc2[col]), 0.f);
                float d1 = fmaxf(fmaf(-2.f, dot1, x2r + sc2[col + 1]), 0.f);
                float t0 = sbt[col] * d0;
                float t1 = sbt[col + 1] * d1;
                float e0 = 0.f, e1 = 0.f;
                if (t0 < 104.5f) e0 = exp_neg(t0);
                if (t1 < 104.5f) e1 = exp_neg(t1);
                __stcs(reinterpret_cast<float2*>(orow + col), make_float2(e0, e1));
            }
        }
    }
}

extern "C" void kernel_launch(void* const* d_in, const int* in_sizes, int n_in,
                              void* d_out, int out_size) {
    const float* x       = (const float*)d_in[0];
    const float* centers = (const float*)d_in[1];
    const float* betas   = (const float*)d_in[2];
    float* out = (float*)d_out;

    int B = in_sizes[0] / D_DIM;   // 65536
    cudaFuncSetAttribute(rbf_main, cudaFuncAttributeMaxDynamicSharedMemorySize, SM_TOTAL);

    rbf_prep_c<<<2, 256>>>(centers);
    rbf_prep_x<<<(B * 8) / 256, 256>>>(x);
    dim3 grid(K_CENT / BN, B / BM);   // N fastest
    rbf_main<<<grid, NTHREADS, SM_TOTAL>>>(betas, out);
}